// round 11
// baseline (speedup 1.0000x reference)
#include <cuda_runtime.h>
#include <cuda_fp16.h>
#include <mma.h>
#include <cstdint>

using namespace nvcuda;

#define NQ      4
#define DIM     16
#define NHEADS  8
#define NLAYERS 2
#define EMBED   32
#define NBASIS  81
#define KPAD    104              // padded K per head (halves); 96 used by MMA
#define KSTEPS  6                // 6 x 16 = 96

// Per-head B operand in matrix_b col_major layout: g_B[h][n][k], fp16.
__device__ half  g_B[NHEADS * 32 * KPAD];
__device__ float g_bias[EMBED];

// ---------------------------------------------------------------------------
// Precompute (R8-validated C pipeline), then fold C and W into per-head fp16
// B matrices M_h[k][n] = sum_q C[h][k][q] * W_out[n][h*4+q], stored [h][n][k].
// Bias kept exact (f32) for the epilogue.
// ---------------------------------------------------------------------------
__global__ void qmha_precompute(const float* __restrict__ params,
                                const float* __restrict__ W,
                                const float* __restrict__ b) {
    __shared__ float Ur[DIM][DIM];
    __shared__ float Ui[DIM][DIM];
    __shared__ float A[NQ][DIM * DIM];
    __shared__ float gc[NLAYERS * NQ * 3];
    __shared__ float gs[NLAYERS * NQ * 3];
    __shared__ float4 sC[NBASIS];

    const int h   = blockIdx.x;
    const int tid = threadIdx.x;

    if (tid < NLAYERS * NQ * 3) {
        const float th = params[h * NLAYERS * NQ * 3 + tid];
        float s, c;
        __sincosf(0.5f * th, &s, &c);
        gc[tid] = c;
        gs[tid] = s;
    }
    __syncthreads();

    if (tid < DIM) {
        float re[DIM], im[DIM];
        #pragma unroll
        for (int s = 0; s < DIM; s++) { re[s] = 0.f; im[s] = 0.f; }
        re[tid] = 1.f;

        for (int l = 0; l < NLAYERS; l++) {
            for (int w = 0; w < NQ; w++) {
                const int mask = 1 << (3 - w);
                const int gi = (l * NQ + w) * 3;
                const float cx = gc[gi + 0], sx = gs[gi + 0];
                const float cy = gc[gi + 1], sy = gs[gi + 1];
                const float cz = gc[gi + 2], sz = gs[gi + 2];
                #pragma unroll
                for (int s0 = 0; s0 < DIM; s0++) {
                    if (s0 & mask) continue;
                    const int s1 = s0 | mask;
                    float r0 = re[s0], i0 = im[s0], r1 = re[s1], i1 = im[s1];
                    float nr0 = cx * r0 + sx * i1;
                    float ni0 = cx * i0 - sx * r1;
                    float nr1 = sx * i0 + cx * r1;
                    float ni1 = -sx * r0 + cx * i1;
                    r0 = nr0; i0 = ni0; r1 = nr1; i1 = ni1;
                    nr0 = cy * r0 - sy * r1;
                    ni0 = cy * i0 - sy * i1;
                    nr1 = sy * r0 + cy * r1;
                    ni1 = sy * i0 + cy * i1;
                    r0 = nr0; i0 = ni0; r1 = nr1; i1 = ni1;
                    re[s0] = cz * r0 + sz * i0;
                    im[s0] = cz * i0 - sz * r0;
                    re[s1] = cz * r1 - sz * i1;
                    im[s1] = cz * i1 + sz * r1;
                }
            }
            #pragma unroll
            for (int e = 0; e < NQ; e++) {
                const int c = e, t = (e + 1) & 3;
                const int cm = 1 << (3 - c), tm = 1 << (3 - t);
                #pragma unroll
                for (int s = 0; s < DIM; s++) {
                    if ((s & cm) && !(s & tm)) {
                        const int s2 = s | tm;
                        float tr = re[s]; re[s] = re[s2]; re[s2] = tr;
                        float ti = im[s]; im[s] = im[s2]; im[s2] = ti;
                    }
                }
            }
        }
        #pragma unroll
        for (int s = 0; s < DIM; s++) { Ur[tid][s] = re[s]; Ui[tid][s] = im[s]; }
    }
    __syncthreads();

    {
        const int p = tid >> 4, q = tid & 15;
        float a0 = 0.f, a1 = 0.f, a2 = 0.f, a3 = 0.f;
        #pragma unroll
        for (int s = 0; s < DIM; s++) {
            float rr = Ur[p][s] * Ur[q][s] + Ui[p][s] * Ui[q][s];
            a0 += (s & 8) ? -rr : rr;
            a1 += (s & 4) ? -rr : rr;
            a2 += (s & 2) ? -rr : rr;
            a3 += (s & 1) ? -rr : rr;
        }
        A[0][tid] = a0; A[1][tid] = a1; A[2][tid] = a2; A[3][tid] = a3;
    }
    __syncthreads();

    if (tid < NBASIS) {
        int kw[4] = {tid / 27, (tid / 9) % 3, (tid / 3) % 3, tid % 3};
        float acc0 = 0.f, acc1 = 0.f, acc2 = 0.f, acc3 = 0.f;
        #pragma unroll
        for (int m = 0; m < 16; m++) {
            int p = 0, q = 0;
            float wgt = 1.0f / 16.0f;
            #pragma unroll
            for (int w = 0; w < 4; w++) {
                const int opt = (m >> w) & 1;
                const int kk = kw[w];
                int a, bb;
                if (kk == 0)      { a = opt; bb = opt; }
                else if (kk == 1) { a = opt; bb = opt; if (opt) wgt = -wgt; }
                else              { a = opt; bb = 1 - opt; }
                p |= a << (3 - w);
                q |= bb << (3 - w);
            }
            acc0 += wgt * A[0][p * 16 + q];
            acc1 += wgt * A[1][p * 16 + q];
            acc2 += wgt * A[2][p * 16 + q];
            acc3 += wgt * A[3][p * 16 + q];
        }
        sC[tid] = make_float4(acc0, acc1, acc2, acc3);
    }
    __syncthreads();

    // Build this head's B: [n][k] fp16 (col-major fragment layout, ld=KPAD)
    for (int idx = tid; idx < 32 * KPAD; idx += 256) {
        const int n = idx / KPAD, k = idx % KPAD;
        float m = 0.f;
        if (k < NBASIS) {
            const float4 c = sC[k];
            const float* wr = W + n * 32 + h * 4;   // W_out[n][h*4 + q]
            m = c.x * wr[0] + c.y * wr[1] + c.z * wr[2] + c.w * wr[3];
        }
        g_B[h * 32 * KPAD + idx] = __float2half_rn(m);
    }
    if (h == 0 && tid < EMBED) g_bias[tid] = b[tid];
}

// ---------------------------------------------------------------------------
// Main: 128 tokens/block, 4 warps. Per head: every thread builds its token's
// 96 fp16 features into the smem A-tile; warps run wmma m16n16k16 (2 M-tiles x
// 2 N-tiles x 6 K-steps) accumulating f32 fragments across all 8 heads.
// Exact f32 bias epilogue through smem.
// SMEM: [0,128) bias | [128, +53248) B (8 heads) | [53376, +26624) A-tile.
// ---------------------------------------------------------------------------
#define BIAS_OFF 0
#define B_OFF    128
#define A_OFF    (B_OFF + NHEADS * 32 * KPAD * 2)       // 53376
#define SMEM_TOTAL (A_OFF + 128 * KPAD * 2)             // 79 KB

__global__ __launch_bounds__(128, 2) void qmha_tc(
    const float4* __restrict__ x,
    float4*       __restrict__ out)
{
    extern __shared__ char smem[];
    const int tid  = threadIdx.x;
    const int warp = tid >> 5;

    // stage B + bias
    {
        float4* dst = (float4*)(smem + B_OFF);
        const float4* src = (const float4*)g_B;
        for (int i = tid; i < NHEADS * 32 * KPAD * 2 / 16; i += 128) dst[i] = src[i];
        if (tid < EMBED) ((float*)(smem + BIAS_OFF))[tid] = g_bias[tid];
    }
    __syncthreads();

    const int t = blockIdx.x * 128 + tid;

    wmma::fragment<wmma::accumulator, 16, 16, 16, float> acc[2][2];
    #pragma unroll
    for (int mt = 0; mt < 2; mt++)
        #pragma unroll
        for (int nt = 0; nt < 2; nt++)
            wmma::fill_fragment(acc[mt][nt], 0.f);

    half* As = (half*)(smem + A_OFF);

    #pragma unroll 1
    for (int h = 0; h < NHEADS; h++) {
        const float4 xv = x[t * 8 + h];
        float c0, s0, c1, s1, c2, s2, c3, s3;
        __sincosf(xv.x, &s0, &c0); __sincosf(xv.y, &s1, &c1);
        __sincosf(xv.z, &s2, &c2); __sincosf(xv.w, &s3, &c3);

        const float A9[9] = {1.f, c1, s1, c0, c0 * c1, c0 * s1, s0, s0 * c1, s0 * s1};
        const float B9[9] = {1.f, c3, s3, c2, c2 * c3, c2 * s3, s2, s2 * c3, s2 * s3};

        uint32_t hi[48];
        #pragma unroll
        for (int c = 0; c < 40; c++) {
            const int k0 = 2 * c, k1 = 2 * c + 1;
            const float f0 = A9[k0 / 9] * B9[k0 % 9];
            const float f1 = A9[k1 / 9] * B9[k1 % 9];
            const __half2 hh = __floats2half2_rn(f0, f1);
            hi[c] = *(const uint32_t*)&hh;
        }
        {
            const float f80 = A9[8] * B9[8];
            const __half2 hh = __floats2half2_rn(f80, 0.f);
            hi[40] = *(const uint32_t*)&hh;
        }
        #pragma unroll
        for (int c = 41; c < 48; c++) hi[c] = 0u;

        // write my token's feature row (96 halves = 12 float4)
        {
            float4* row = (float4*)(As + tid * KPAD);
            #pragma unroll
            for (int v = 0; v < 12; v++)
                row[v] = make_float4(__uint_as_float(hi[4 * v + 0]),
                                     __uint_as_float(hi[4 * v + 1]),
                                     __uint_as_float(hi[4 * v + 2]),
                                     __uint_as_float(hi[4 * v + 3]));
        }
        __syncthreads();

        const half* Bh = (const half*)(smem + B_OFF) + h * 32 * KPAD;
        #pragma unroll
        for (int ks = 0; ks < KSTEPS; ks++) {
            wmma::fragment<wmma::matrix_a, 16, 16, 16, half, wmma::row_major> af[2];
            wmma::fragment<wmma::matrix_b, 16, 16, 16, half, wmma::col_major> bf[2];
            wmma::load_matrix_sync(af[0], As + (warp * 32 +  0) * KPAD + ks * 16, KPAD);
            wmma::load_matrix_sync(af[1], As + (warp * 32 + 16) * KPAD + ks * 16, KPAD);
            wmma::load_matrix_sync(bf[0], Bh + ks * 16 +  0 * KPAD, KPAD);
            wmma::load_matrix_sync(bf[1], Bh + ks * 16 + 16 * KPAD, KPAD);
            #pragma unroll
            for (int mt = 0; mt < 2; mt++)
                #pragma unroll
                for (int nt = 0; nt < 2; nt++)
                    wmma::mma_sync(acc[mt][nt], af[mt], bf[nt], acc[mt][nt]);
        }
        __syncthreads();   // A-tile reused next head
    }

    // epilogue: fragments -> smem (f32, ld=40), + exact bias, -> global
    float* Cs = (float*)(smem + A_OFF);   // 128 x 40 f32 = 20.5 KB (fits A region)
    #pragma unroll
    for (int mt = 0; mt < 2; mt++)
        #pragma unroll
        for (int nt = 0; nt < 2; nt++)
            wmma::store_matrix_sync(Cs + (warp * 32 + mt * 16) * 40 + nt * 16,
                                    acc[mt][nt], 40, wmma::mem_row_major);
    __syncthreads();

    {
        const float4* bs4 = (const float4*)(smem + BIAS_OFF);
        const float* crow = Cs + tid * 40;
        #pragma unroll
        for (int e4 = 0; e4 < 8; e4++) {
            const float4 bv = bs4[e4];
            out[t * 8 + e4] = make_float4(crow[4 * e4 + 0] + bv.x,
                                          crow[4 * e4 + 1] + bv.y,
                                          crow[4 * e4 + 2] + bv.z,
                                          crow[4 * e4 + 3] + bv.w);
        }
    }
}

extern "C" void kernel_launch(void* const* d_in, const int* in_sizes, int n_in,
                              void* d_out, int out_size) {
    const float* x      = (const float*)d_in[0];
    const float* params = (const float*)d_in[1];
    const float* W      = (const float*)d_in[2];
    const float* b      = (const float*)d_in[3];

    const int tokens = in_sizes[0] / EMBED;   // 131072

    cudaFuncSetAttribute(qmha_tc, cudaFuncAttributeMaxDynamicSharedMemorySize, SMEM_TOTAL);

    qmha_precompute<<<NHEADS, 256>>>(params, W, b);

    const int blocks = tokens / 128;          // 1024
    qmha_tc<<<blocks, 128, SMEM_TOTAL>>>((const float4*)x, (float4*)d_out);
}

// round 12
// speedup vs baseline: 1.0339x; 1.0339x over previous
#include <cuda_runtime.h>
#include <cuda_fp16.h>
#include <mma.h>
#include <cstdint>

using namespace nvcuda;

#define NQ      4
#define DIM     16
#define NHEADS  8
#define NLAYERS 2
#define EMBED   32
#define NBASIS  81
#define KPAD    104              // padded K per head (halves); 96 used by MMA
#define KSTEPS  6                // 6 x 16 = 96

// Per-head B operand in matrix_b col_major layout: g_B[h][n][k], fp16.
// Read directly by wmma from global (identical across blocks -> L1-cached).
__device__ half  g_B[NHEADS * 32 * KPAD];
__device__ float g_bias[EMBED];

// ---------------------------------------------------------------------------
// Precompute (R8-validated C pipeline), then fold C and W into per-head fp16
// B matrices M_h[k][n] = sum_q C[h][k][q] * W_out[n][h*4+q], stored [h][n][k].
// Bias kept exact (f32) for the epilogue.
// ---------------------------------------------------------------------------
__global__ void qmha_precompute(const float* __restrict__ params,
                                const float* __restrict__ W,
                                const float* __restrict__ b) {
    __shared__ float Ur[DIM][DIM];
    __shared__ float Ui[DIM][DIM];
    __shared__ float A[NQ][DIM * DIM];
    __shared__ float gc[NLAYERS * NQ * 3];
    __shared__ float gs[NLAYERS * NQ * 3];
    __shared__ float4 sC[NBASIS];

    const int h   = blockIdx.x;
    const int tid = threadIdx.x;

    if (tid < NLAYERS * NQ * 3) {
        const float th = params[h * NLAYERS * NQ * 3 + tid];
        float s, c;
        __sincosf(0.5f * th, &s, &c);
        gc[tid] = c;
        gs[tid] = s;
    }
    __syncthreads();

    if (tid < DIM) {
        float re[DIM], im[DIM];
        #pragma unroll
        for (int s = 0; s < DIM; s++) { re[s] = 0.f; im[s] = 0.f; }
        re[tid] = 1.f;

        for (int l = 0; l < NLAYERS; l++) {
            for (int w = 0; w < NQ; w++) {
                const int mask = 1 << (3 - w);
                const int gi = (l * NQ + w) * 3;
                const float cx = gc[gi + 0], sx = gs[gi + 0];
                const float cy = gc[gi + 1], sy = gs[gi + 1];
                const float cz = gc[gi + 2], sz = gs[gi + 2];
                #pragma unroll
                for (int s0 = 0; s0 < DIM; s0++) {
                    if (s0 & mask) continue;
                    const int s1 = s0 | mask;
                    float r0 = re[s0], i0 = im[s0], r1 = re[s1], i1 = im[s1];
                    float nr0 = cx * r0 + sx * i1;
                    float ni0 = cx * i0 - sx * r1;
                    float nr1 = sx * i0 + cx * r1;
                    float ni1 = -sx * r0 + cx * i1;
                    r0 = nr0; i0 = ni0; r1 = nr1; i1 = ni1;
                    nr0 = cy * r0 - sy * r1;
                    ni0 = cy * i0 - sy * i1;
                    nr1 = sy * r0 + cy * r1;
                    ni1 = sy * i0 + cy * i1;
                    r0 = nr0; i0 = ni0; r1 = nr1; i1 = ni1;
                    re[s0] = cz * r0 + sz * i0;
                    im[s0] = cz * i0 - sz * r0;
                    re[s1] = cz * r1 - sz * i1;
                    im[s1] = cz * i1 + sz * r1;
                }
            }
            #pragma unroll
            for (int e = 0; e < NQ; e++) {
                const int c = e, t = (e + 1) & 3;
                const int cm = 1 << (3 - c), tm = 1 << (3 - t);
                #pragma unroll
                for (int s = 0; s < DIM; s++) {
                    if ((s & cm) && !(s & tm)) {
                        const int s2 = s | tm;
                        float tr = re[s]; re[s] = re[s2]; re[s2] = tr;
                        float ti = im[s]; im[s] = im[s2]; im[s2] = ti;
                    }
                }
            }
        }
        #pragma unroll
        for (int s = 0; s < DIM; s++) { Ur[tid][s] = re[s]; Ui[tid][s] = im[s]; }
    }
    __syncthreads();

    {
        const int p = tid >> 4, q = tid & 15;
        float a0 = 0.f, a1 = 0.f, a2 = 0.f, a3 = 0.f;
        #pragma unroll
        for (int s = 0; s < DIM; s++) {
            float rr = Ur[p][s] * Ur[q][s] + Ui[p][s] * Ui[q][s];
            a0 += (s & 8) ? -rr : rr;
            a1 += (s & 4) ? -rr : rr;
            a2 += (s & 2) ? -rr : rr;
            a3 += (s & 1) ? -rr : rr;
        }
        A[0][tid] = a0; A[1][tid] = a1; A[2][tid] = a2; A[3][tid] = a3;
    }
    __syncthreads();

    if (tid < NBASIS) {
        int kw[4] = {tid / 27, (tid / 9) % 3, (tid / 3) % 3, tid % 3};
        float acc0 = 0.f, acc1 = 0.f, acc2 = 0.f, acc3 = 0.f;
        #pragma unroll
        for (int m = 0; m < 16; m++) {
            int p = 0, q = 0;
            float wgt = 1.0f / 16.0f;
            #pragma unroll
            for (int w = 0; w < 4; w++) {
                const int opt = (m >> w) & 1;
                const int kk = kw[w];
                int a, bb;
                if (kk == 0)      { a = opt; bb = opt; }
                else if (kk == 1) { a = opt; bb = opt; if (opt) wgt = -wgt; }
                else              { a = opt; bb = 1 - opt; }
                p |= a << (3 - w);
                q |= bb << (3 - w);
            }
            acc0 += wgt * A[0][p * 16 + q];
            acc1 += wgt * A[1][p * 16 + q];
            acc2 += wgt * A[2][p * 16 + q];
            acc3 += wgt * A[3][p * 16 + q];
        }
        sC[tid] = make_float4(acc0, acc1, acc2, acc3);
    }
    __syncthreads();

    // Build this head's B: [n][k] fp16 (col-major fragment layout, ld=KPAD)
    for (int idx = tid; idx < 32 * KPAD; idx += 256) {
        const int n = idx / KPAD, k = idx % KPAD;
        float m = 0.f;
        if (k < NBASIS) {
            const float4 c = sC[k];
            const float* wr = W + n * 32 + h * 4;   // W_out[n][h*4 + q]
            m = c.x * wr[0] + c.y * wr[1] + c.z * wr[2] + c.w * wr[3];
        }
        g_B[h * 32 * KPAD + idx] = __float2half_rn(m);
    }
    if (h == 0 && tid < EMBED) g_bias[tid] = b[tid];
}

// ---------------------------------------------------------------------------
// Main: 128 tokens/block, 4 warps. Per head: every thread builds its token's
// 96 fp16 features into the smem A-tile; warps run wmma m16n16k16 (2 M-tiles x
// 2 N-tiles x 6 K-steps). B fragments load DIRECTLY FROM GLOBAL (L1-cached,
// same addresses for all blocks). Smem = bias + A tile only (26 KB) ->
// 5 blocks/SM resident (occupancy 12% -> ~42%).
// ---------------------------------------------------------------------------
#define BIAS_OFF 0
#define A_OFF    128
#define SMEM_TOTAL (A_OFF + 128 * KPAD * 2)             // 26752 B

__global__ __launch_bounds__(128, 5) void qmha_tc(
    const float4* __restrict__ x,
    float4*       __restrict__ out)
{
    extern __shared__ char smem[];
    const int tid  = threadIdx.x;
    const int warp = tid >> 5;

    if (tid < EMBED) ((float*)(smem + BIAS_OFF))[tid] = g_bias[tid];
    __syncthreads();

    const int t = blockIdx.x * 128 + tid;

    wmma::fragment<wmma::accumulator, 16, 16, 16, float> acc[2][2];
    #pragma unroll
    for (int mt = 0; mt < 2; mt++)
        #pragma unroll
        for (int nt = 0; nt < 2; nt++)
            wmma::fill_fragment(acc[mt][nt], 0.f);

    half* As = (half*)(smem + A_OFF);

    #pragma unroll 1
    for (int h = 0; h < NHEADS; h++) {
        const float4 xv = x[t * 8 + h];
        float c0, s0, c1, s1, c2, s2, c3, s3;
        __sincosf(xv.x, &s0, &c0); __sincosf(xv.y, &s1, &c1);
        __sincosf(xv.z, &s2, &c2); __sincosf(xv.w, &s3, &c3);

        const float A9[9] = {1.f, c1, s1, c0, c0 * c1, c0 * s1, s0, s0 * c1, s0 * s1};
        const float B9[9] = {1.f, c3, s3, c2, c2 * c3, c2 * s3, s2, s2 * c3, s2 * s3};

        uint32_t hi[48];
        #pragma unroll
        for (int c = 0; c < 40; c++) {
            const int k0 = 2 * c, k1 = 2 * c + 1;
            const float f0 = A9[k0 / 9] * B9[k0 % 9];
            const float f1 = A9[k1 / 9] * B9[k1 % 9];
            const __half2 hh = __floats2half2_rn(f0, f1);
            hi[c] = *(const uint32_t*)&hh;
        }
        {
            const float f80 = A9[8] * B9[8];
            const __half2 hh = __floats2half2_rn(f80, 0.f);
            hi[40] = *(const uint32_t*)&hh;
        }
        #pragma unroll
        for (int c = 41; c < 48; c++) hi[c] = 0u;

        // write my token's feature row (96 halves = 12 float4)
        {
            float4* row = (float4*)(As + tid * KPAD);
            #pragma unroll
            for (int v = 0; v < 12; v++)
                row[v] = make_float4(__uint_as_float(hi[4 * v + 0]),
                                     __uint_as_float(hi[4 * v + 1]),
                                     __uint_as_float(hi[4 * v + 2]),
                                     __uint_as_float(hi[4 * v + 3]));
        }
        __syncthreads();

        const half* Bh = g_B + h * 32 * KPAD;   // GLOBAL operand (L1-cached)
        #pragma unroll
        for (int ks = 0; ks < KSTEPS; ks++) {
            wmma::fragment<wmma::matrix_a, 16, 16, 16, half, wmma::row_major> af[2];
            wmma::fragment<wmma::matrix_b, 16, 16, 16, half, wmma::col_major> bf[2];
            wmma::load_matrix_sync(af[0], As + (warp * 32 +  0) * KPAD + ks * 16, KPAD);
            wmma::load_matrix_sync(af[1], As + (warp * 32 + 16) * KPAD + ks * 16, KPAD);
            wmma::load_matrix_sync(bf[0], Bh + ks * 16 +  0 * KPAD, KPAD);
            wmma::load_matrix_sync(bf[1], Bh + ks * 16 + 16 * KPAD, KPAD);
            #pragma unroll
            for (int mt = 0; mt < 2; mt++)
                #pragma unroll
                for (int nt = 0; nt < 2; nt++)
                    wmma::mma_sync(acc[mt][nt], af[mt], bf[nt], acc[mt][nt]);
        }
        __syncthreads();   // A-tile reused next head
    }

    // epilogue: fragments -> smem (f32, ld=40), + exact bias, -> global
    float* Cs = (float*)(smem + A_OFF);   // 128 x 40 f32 = 20.5 KB (fits A region)
    #pragma unroll
    for (int mt = 0; mt < 2; mt++)
        #pragma unroll
        for (int nt = 0; nt < 2; nt++)
            wmma::store_matrix_sync(Cs + (warp * 32 + mt * 16) * 40 + nt * 16,
                                    acc[mt][nt], 40, wmma::mem_row_major);
    __syncthreads();

    {
        const float4* bs4 = (const float4*)(smem + BIAS_OFF);
        const float* crow = Cs + tid * 40;
        #pragma unroll
        for (int e4 = 0; e4 < 8; e4++) {
            const float4 bv = bs4[e4];
            out[t * 8 + e4] = make_float4(crow[4 * e4 + 0] + bv.x,
                                          crow[4 * e4 + 1] + bv.y,
                                          crow[4 * e4 + 2] + bv.z,
                                          crow[4 * e4 + 3] + bv.w);
        }
    }
}

extern "C" void kernel_launch(void* const* d_in, const int* in_sizes, int n_in,
                              void* d_out, int out_size) {
    const float* x      = (const float*)d_in[0];
    const float* params = (const float*)d_in[1];
    const float* W      = (const float*)d_in[2];
    const float* b      = (const float*)d_in[3];

    const int tokens = in_sizes[0] / EMBED;   // 131072

    cudaFuncSetAttribute(qmha_tc, cudaFuncAttributeMaxDynamicSharedMemorySize, SMEM_TOTAL);

    qmha_precompute<<<NHEADS, 256>>>(params, W, b);

    const int blocks = tokens / 128;          // 1024
    qmha_tc<<<blocks, 128, SMEM_TOTAL>>>((const float4*)x, (float4*)d_out);
}